// round 3
// baseline (speedup 1.0000x reference)
#include <cuda_runtime.h>
#include <math.h>
#include <stdint.h>

// Problem dims (fixed by the reference)
#define B_   256
#define T_   64
#define F_   2048
#define P_   512
#define H_   512
#define G4H  2048          // 4*H
#define BT   16384         // B*T

// ---------------- scratch (static device memory; no cudaMalloc allowed) ----
__device__ float g_v[(size_t)BT * P_];          // embedded features, row = b*T+t
__device__ float g_A[2][(size_t)BT * G4H];      // precomputed x@W_ih.T + b_ih + b_hh
__device__ float g_h[2][2][B_ * H_];            // [lstm][parity buffer]
__device__ float g_c[2][B_ * H_];

// ---------------------------------------------------------------------------
// Generic NT SGEMM: C[m,n] = sum_k A[m,k]*Bw[n,k] + bias0[n] (+ bias1[n])
// BM=BN=128, BK=16, 256 threads, 8x8 per-thread tile.
// M, N, K must be multiples of the tile dims (true for all our shapes).
// ---------------------------------------------------------------------------
template<int BM, int BN, int BK>
__global__ __launch_bounds__(256)
void sgemm_nt(const float* __restrict__ A, int lda,
              const float* __restrict__ Bw, int ldb,
              const float* __restrict__ bias0,
              const float* __restrict__ bias1,
              float* __restrict__ C, int ldc, int K)
{
    __shared__ float As[BK][BM + 4];
    __shared__ float Bs[BK][BN + 4];

    const int tid = threadIdx.x;
    const int tx = tid & 15;          // 0..15 -> N direction
    const int ty = tid >> 4;          // 0..15 -> M direction
    const int row0 = blockIdx.y * BM;
    const int col0 = blockIdx.x * BN;

    float acc[8][8] = {};

    constexpr int A_LD = (BM * BK) / (4 * 256);   // float4 loads per thread
    constexpr int B_LD = (BN * BK) / (4 * 256);

    for (int k0 = 0; k0 < K; k0 += BK) {
        #pragma unroll
        for (int i = 0; i < A_LD; i++) {
            int f  = tid + i * 256;
            int r  = f >> 2;                  // / (BK/4)
            int kq = (f & 3) << 2;
            float4 v = *reinterpret_cast<const float4*>(
                &A[(size_t)(row0 + r) * lda + k0 + kq]);
            As[kq + 0][r] = v.x; As[kq + 1][r] = v.y;
            As[kq + 2][r] = v.z; As[kq + 3][r] = v.w;
        }
        #pragma unroll
        for (int i = 0; i < B_LD; i++) {
            int f  = tid + i * 256;
            int r  = f >> 2;
            int kq = (f & 3) << 2;
            float4 v = *reinterpret_cast<const float4*>(
                &Bw[(size_t)(col0 + r) * ldb + k0 + kq]);
            Bs[kq + 0][r] = v.x; Bs[kq + 1][r] = v.y;
            Bs[kq + 2][r] = v.z; Bs[kq + 3][r] = v.w;
        }
        __syncthreads();

        #pragma unroll
        for (int k = 0; k < BK; k++) {
            float a[8], b[8];
            *reinterpret_cast<float4*>(&a[0]) =
                *reinterpret_cast<const float4*>(&As[k][ty * 8]);
            *reinterpret_cast<float4*>(&a[4]) =
                *reinterpret_cast<const float4*>(&As[k][ty * 8 + 4]);
            *reinterpret_cast<float4*>(&b[0]) =
                *reinterpret_cast<const float4*>(&Bs[k][tx * 8]);
            *reinterpret_cast<float4*>(&b[4]) =
                *reinterpret_cast<const float4*>(&Bs[k][tx * 8 + 4]);
            #pragma unroll
            for (int i = 0; i < 8; i++)
                #pragma unroll
                for (int j = 0; j < 8; j++)
                    acc[i][j] = fmaf(a[i], b[j], acc[i][j]);
        }
        __syncthreads();
    }

    // epilogue: add bias, store
    float bcol[8];
    #pragma unroll
    for (int j = 0; j < 8; j++) {
        int c = col0 + tx * 8 + j;
        float bv = bias0 ? bias0[c] : 0.0f;
        if (bias1) bv += bias1[c];
        bcol[j] = bv;
    }
    #pragma unroll
    for (int i = 0; i < 8; i++) {
        int r = row0 + ty * 8 + i;
        #pragma unroll
        for (int j = 0; j < 8; j += 4) {
            int c = col0 + tx * 8 + j;
            float4 o;
            o.x = acc[i][j + 0] + bcol[j + 0];
            o.y = acc[i][j + 1] + bcol[j + 1];
            o.z = acc[i][j + 2] + bcol[j + 2];
            o.w = acc[i][j + 3] + bcol[j + 3];
            *reinterpret_cast<float4*>(&C[(size_t)r * ldc + c]) = o;
        }
    }
}

// ---------------------------------------------------------------------------
// Fused per-step LSTM kernel (both LSTMs via blockIdx.z):
//   For each (b, j): g_{i,f,g,o} = Apre[b,toff,gate*H+j] + sum_k h[b,k]*W_hh[gate*H+j,k]
//   then apply the cell and write c, h (double-buffered), and the output.
// Tile: 64 batch rows x 32 j-cols x 4 gates. 256 threads:
//   jt = tid&15 -> 2 j each, bt = tid>>4 -> 4 rows each. 32 acc/thread.
// Grid: (512/32, 256/64, 2) = 128 CTAs (one wave on 148 SMs).
// h is read from buffer (t&1) and written to buffer (t&1)^1, so there is no
// intra-launch RAW hazard between CTAs.
// ---------------------------------------------------------------------------
__global__ __launch_bounds__(256)
void lstm_step(const float* __restrict__ Whh1,
               const float* __restrict__ Whh2,
               float* __restrict__ out, int t)
{
    const int z = blockIdx.z;
    const float* __restrict__ W = z ? Whh2 : Whh1;
    const int toff = z ? (T_ - 1 - t) : t;
    const int rbuf = t & 1;
    const float* __restrict__ hread  = g_h[z][rbuf];
    float* __restrict__       hwrite = g_h[z][rbuf ^ 1];

    __shared__ float Hs[16][68];      // [k][row], 64 rows + pad (272B rows, 16B aligned)
    __shared__ float Ws[4][16][34];   // [gate][k][col], 32 cols + pad (136B rows, 8B aligned)

    const int tid  = threadIdx.x;
    const int row0 = blockIdx.y * 64;     // batch
    const int col0 = blockIdx.x * 32;     // j within gate
    const int jt   = tid & 15;            // 2 j-cols each
    const int bt   = tid >> 4;            // 4 batch rows each

    float acc[4][4][2] = {};              // [gate][brow][j]

    for (int k0 = 0; k0 < H_; k0 += 16) {
        {   // H tile: 64x16 floats = 256 float4, one per thread
            int r = tid >> 2, kq = (tid & 3) << 2;
            float4 v = *reinterpret_cast<const float4*>(
                &hread[(row0 + r) * H_ + k0 + kq]);
            Hs[kq + 0][r] = v.x; Hs[kq + 1][r] = v.y;
            Hs[kq + 2][r] = v.z; Hs[kq + 3][r] = v.w;
        }
        #pragma unroll
        for (int i = 0; i < 2; i++) {   // W tiles: 4x32x16 floats = 512 float4
            int f  = tid + i * 256;
            int g  = f >> 7;            // 128 float4 per gate tile
            int r  = (f >> 2) & 31;
            int kq = (f & 3) << 2;
            float4 v = *reinterpret_cast<const float4*>(
                &W[(size_t)(g * H_ + col0 + r) * H_ + k0 + kq]);
            Ws[g][kq + 0][r] = v.x; Ws[g][kq + 1][r] = v.y;
            Ws[g][kq + 2][r] = v.z; Ws[g][kq + 3][r] = v.w;
        }
        __syncthreads();

        #pragma unroll
        for (int k = 0; k < 16; k++) {
            float4 a4 = *reinterpret_cast<const float4*>(&Hs[k][bt * 4]);
            float a[4] = {a4.x, a4.y, a4.z, a4.w};
            #pragma unroll
            for (int g = 0; g < 4; g++) {
                float2 b2 = *reinterpret_cast<const float2*>(&Ws[g][k][jt * 2]);
                #pragma unroll
                for (int i = 0; i < 4; i++) {
                    acc[g][i][0] = fmaf(a[i], b2.x, acc[g][i][0]);
                    acc[g][i][1] = fmaf(a[i], b2.y, acc[g][i][1]);
                }
            }
        }
        __syncthreads();
    }

    // Epilogue: add precomputed input contribution, run the cell, write back.
    const int j0 = col0 + jt * 2;
    #pragma unroll
    for (int i = 0; i < 4; i++) {
        const int brow = row0 + bt * 4 + i;
        const float* __restrict__ Apre =
            g_A[z] + ((size_t)brow * T_ + toff) * (size_t)G4H;

        float2 ai = *reinterpret_cast<const float2*>(&Apre[0 * H_ + j0]);
        float2 af = *reinterpret_cast<const float2*>(&Apre[1 * H_ + j0]);
        float2 ag = *reinterpret_cast<const float2*>(&Apre[2 * H_ + j0]);
        float2 ao = *reinterpret_cast<const float2*>(&Apre[3 * H_ + j0]);
        float2 c2 = *reinterpret_cast<const float2*>(&g_c[z][brow * H_ + j0]);

        float gi0 = acc[0][i][0] + ai.x, gi1 = acc[0][i][1] + ai.y;
        float gf0 = acc[1][i][0] + af.x, gf1 = acc[1][i][1] + af.y;
        float gg0 = acc[2][i][0] + ag.x, gg1 = acc[2][i][1] + ag.y;
        float go0 = acc[3][i][0] + ao.x, go1 = acc[3][i][1] + ao.y;

        float si0 = 1.0f / (1.0f + expf(-gi0));
        float sf0 = 1.0f / (1.0f + expf(-gf0));
        float so0 = 1.0f / (1.0f + expf(-go0));
        float si1 = 1.0f / (1.0f + expf(-gi1));
        float sf1 = 1.0f / (1.0f + expf(-gf1));
        float so1 = 1.0f / (1.0f + expf(-go1));

        float cn0 = sf0 * c2.x + si0 * tanhf(gg0);
        float cn1 = sf1 * c2.y + si1 * tanhf(gg1);
        float hn0 = so0 * tanhf(cn0);
        float hn1 = so1 * tanhf(cn1);

        *reinterpret_cast<float2*>(&g_c[z][brow * H_ + j0]) = make_float2(cn0, cn1);
        *reinterpret_cast<float2*>(&hwrite[brow * H_ + j0]) = make_float2(hn0, hn1);

        size_t oidx = (size_t)z * B_ * T_ * H_
                    + (size_t)brow * T_ * H_ + (size_t)toff * H_ + j0;
        *reinterpret_cast<float2*>(&out[oidx]) = make_float2(hn0, hn1);
    }
}

__global__ void init_state_kernel()
{
    int idx = blockIdx.x * blockDim.x + threadIdx.x;
    if (idx < B_ * H_) {
        g_h[0][0][idx] = 0.0f; g_h[1][0][idx] = 0.0f;
        g_c[0][idx]    = 0.0f; g_c[1][idx]    = 0.0f;
    }
}

// ---------------------------------------------------------------------------
extern "C" void kernel_launch(void* const* d_in, const int* in_sizes, int n_in,
                              void* d_out, int out_size)
{
    const float* video = (const float*)d_in[0];   // (B, T, F)
    const float* W_e   = (const float*)d_in[1];   // (P, F)
    const float* b_e   = (const float*)d_in[2];   // (P,)
    const float* W_ih1 = (const float*)d_in[3];   // (4H, P)
    const float* W_hh1 = (const float*)d_in[4];   // (4H, H)
    const float* b_ih1 = (const float*)d_in[5];
    const float* b_hh1 = (const float*)d_in[6];
    const float* W_ih2 = (const float*)d_in[7];
    const float* W_hh2 = (const float*)d_in[8];
    const float* b_ih2 = (const float*)d_in[9];
    const float* b_hh2 = (const float*)d_in[10];
    float* out = (float*)d_out;                   // [lstm1_out | lstm2_out], fp32

    float *dv = nullptr, *dA = nullptr;
    cudaGetSymbolAddress((void**)&dv, g_v);
    cudaGetSymbolAddress((void**)&dA, g_A);
    float* dA0 = dA;
    float* dA1 = dA + (size_t)BT * G4H;

    // Phase 1: v = X @ W_e.T + b_e     (M=16384, N=512, K=2048)
    sgemm_nt<128,128,16><<<dim3(P_ / 128, BT / 128), 256>>>(
        video, F_, W_e, F_, b_e, nullptr, dv, P_, F_);

    // Phase 2: A = v @ W_ih.T + (b_ih + b_hh)   (M=16384, N=2048, K=512) x2
    sgemm_nt<128,128,16><<<dim3(G4H / 128, BT / 128), 256>>>(
        dv, P_, W_ih1, P_, b_ih1, b_hh1, dA0, G4H, P_);
    sgemm_nt<128,128,16><<<dim3(G4H / 128, BT / 128), 256>>>(
        dv, P_, W_ih2, P_, b_ih2, b_hh2, dA1, G4H, P_);

    // Zero h/c
    init_state_kernel<<<(B_ * H_ + 255) / 256, 256>>>();

    // Phase 3: 64 sequential fused steps, both LSTMs per launch
    for (int t = 0; t < T_; t++) {
        lstm_step<<<dim3(H_ / 32, B_ / 64, 2), 256>>>(W_hh1, W_hh2, out, t);
    }
}

// round 7
// speedup vs baseline: 1.0418x; 1.0418x over previous
#include <cuda_runtime.h>
#include <cuda_bf16.h>
#include <math.h>
#include <stdint.h>

// Problem dims (fixed by the reference)
#define B_   256
#define T_   64
#define F_   2048
#define P_   512
#define H_   512
#define G4H  2048          // 4*H
#define BT   16384         // B*T

// ---------------- scratch (static device memory; no cudaMalloc allowed) ----
__device__ __nv_bfloat16 g_vidS[(size_t)BT * 3 * F_];     // video split  16384x6144
__device__ __nv_bfloat16 g_WeS[(size_t)P_ * 3 * F_];      // W_e split    512x6144
__device__ __nv_bfloat16 g_WihS[2][(size_t)G4H * 3 * P_]; // W_ih split   2048x1536 x2
__device__ __nv_bfloat16 g_vS[(size_t)BT * 3 * P_];       // v split      16384x1536
__device__ float g_A[2][(size_t)BT * G4H];                // gate preacts (fp32)
__device__ float g_h[2][2][B_ * H_];                      // [lstm][parity]
__device__ float g_c[2][B_ * H_];

__device__ __forceinline__ uint32_t smem_u32(const void* p) {
    uint32_t a;
    asm("{ .reg .u64 t; cvta.to.shared.u64 t, %1; cvt.u32.u64 %0, t; }"
        : "=r"(a) : "l"(p));
    return a;
}

// ============================ split conversion =============================
// src (M x K fp32) -> dst (M x 3K bf16). pattern 0 (A): [hi | lo | hi]
//                                        pattern 1 (B): [hi | hi | lo]
__global__ __launch_bounds__(256)
void split3_kernel(const float* __restrict__ src, __nv_bfloat16* __restrict__ dst,
                   int kshift, int pattern, size_t total)
{
    size_t i = ((size_t)blockIdx.x * blockDim.x + threadIdx.x) * 4;
    if (i >= total) return;
    int K = 1 << kshift;
    size_t m = i >> kshift;
    int k = (int)(i & (size_t)(K - 1));
    float4 v = *reinterpret_cast<const float4*>(src + i);

    __nv_bfloat162 h0, h1, l0, l1;
    h0.x = __float2bfloat16_rn(v.x); h0.y = __float2bfloat16_rn(v.y);
    h1.x = __float2bfloat16_rn(v.z); h1.y = __float2bfloat16_rn(v.w);
    l0.x = __float2bfloat16_rn(v.x - __bfloat162float(h0.x));
    l0.y = __float2bfloat16_rn(v.y - __bfloat162float(h0.y));
    l1.x = __float2bfloat16_rn(v.z - __bfloat162float(h1.x));
    l1.y = __float2bfloat16_rn(v.w - __bfloat162float(h1.y));

    __nv_bfloat16* row = dst + m * (size_t)(3 * K);
    *reinterpret_cast<__nv_bfloat162*>(row + k)     = h0;
    *reinterpret_cast<__nv_bfloat162*>(row + k + 2) = h1;
    if (pattern == 0) {   // A: hi, lo, hi
        *reinterpret_cast<__nv_bfloat162*>(row + K + k)         = l0;
        *reinterpret_cast<__nv_bfloat162*>(row + K + k + 2)     = l1;
        *reinterpret_cast<__nv_bfloat162*>(row + 2 * K + k)     = h0;
        *reinterpret_cast<__nv_bfloat162*>(row + 2 * K + k + 2) = h1;
    } else {              // B: hi, hi, lo
        *reinterpret_cast<__nv_bfloat162*>(row + K + k)         = h0;
        *reinterpret_cast<__nv_bfloat162*>(row + K + k + 2)     = h1;
        *reinterpret_cast<__nv_bfloat162*>(row + 2 * K + k)     = l0;
        *reinterpret_cast<__nv_bfloat162*>(row + 2 * K + k + 2) = l1;
    }
}

// ==================== mma.sync bf16 GEMM (base sm_100 ISA) =================
// C[m,n] = sum_k A[m,k]*B[n,k] (+bias0[n]+bias1[n]).  A: MxKt, B: NglobxKt.
// Tile 128(M) x 128(N) x 32(K). 256 threads = 8 warps in 2(M) x 4(N).
// Warp tile 64x32 = 4 m16 frags x 4 n8 frags, mma.m16n8k16 bf16 -> f32.
#define PAD 40   // smem row stride in bf16 (32 data + 8 pad = 80B, conflict-free)

__global__ __launch_bounds__(256)
void gemm_mma_split(const __nv_bfloat16* __restrict__ Amat,
                    const __nv_bfloat16* __restrict__ Bmat,
                    int Kt, int Nglob,
                    const float* __restrict__ bias0,
                    const float* __restrict__ bias1,
                    float* __restrict__ C,
                    __nv_bfloat16* __restrict__ Csplit)  // [hi|lo|hi], rows 3*Nglob
{
    __shared__ __nv_bfloat16 As[128 * PAD];
    __shared__ __nv_bfloat16 Bs[128 * PAD];

    const int tid    = threadIdx.x;
    const int lane   = tid & 31;
    const int wid    = tid >> 5;
    const int warp_m = wid >> 2;          // 0..1  -> M offset 64*warp_m
    const int warp_n = wid & 3;           // 0..3  -> N offset 32*warp_n
    const int row0   = blockIdx.y * 128;
    const int col0   = blockIdx.x * 128;

    const uint32_t sA = smem_u32(As);
    const uint32_t sB = smem_u32(Bs);

    float c[4][4][4];
    #pragma unroll
    for (int i = 0; i < 4; i++)
        #pragma unroll
        for (int j = 0; j < 4; j++)
            #pragma unroll
            for (int q = 0; q < 4; q++) c[i][j][q] = 0.0f;

    // ldmatrix source addresses (fixed per thread; k-step adds byte offset)
    // A x4: row = warp_m*64 + mf*16 + (lane&15), col8 = (lane>>4)
    const int a_row = warp_m * 64 + (lane & 15);
    const uint32_t a_base = sA + (uint32_t)(a_row * PAD + (lane >> 4) * 8) * 2;
    // B x2: row = warp_n*32 + nf*8 + (lane&7), col8 = (lane>>3)&1
    const int b_row = warp_n * 32 + (lane & 7);
    const uint32_t b_base = sB + (uint32_t)(b_row * PAD + ((lane >> 3) & 1) * 8) * 2;

    const int nblk = Kt >> 5;             // Kt / 32
    for (int kb = 0; kb < nblk; kb++) {
        // ---- global -> smem: A and B tiles are 128 rows x 32 bf16 (64B/row)
        {
            const __nv_bfloat16* Ag = Amat + (size_t)row0 * Kt + kb * 32;
            const __nv_bfloat16* Bg = Bmat + (size_t)col0 * Kt + kb * 32;
            #pragma unroll
            for (int i = 0; i < 2; i++) {
                int f   = tid + i * 256;
                int r   = f >> 2;
                int seg = f & 3;
                *reinterpret_cast<uint4*>(&As[r * PAD + seg * 8]) =
                    *reinterpret_cast<const uint4*>(Ag + (size_t)r * Kt + seg * 8);
                *reinterpret_cast<uint4*>(&Bs[r * PAD + seg * 8]) =
                    *reinterpret_cast<const uint4*>(Bg + (size_t)r * Kt + seg * 8);
            }
        }
        __syncthreads();

        #pragma unroll
        for (int ks = 0; ks < 2; ks++) {
            const uint32_t koff = (uint32_t)(ks * 16) * 2;   // byte offset
            uint32_t a[4][4];
            #pragma unroll
            for (int mf = 0; mf < 4; mf++) {
                uint32_t addr = a_base + (uint32_t)(mf * 16 * PAD) * 2 + koff;
                asm volatile(
                    "ldmatrix.sync.aligned.m8n8.x4.shared.b16 {%0,%1,%2,%3}, [%4];"
                    : "=r"(a[mf][0]), "=r"(a[mf][1]), "=r"(a[mf][2]), "=r"(a[mf][3])
                    : "r"(addr));
            }
            uint32_t b[4][2];
            #pragma unroll
            for (int nf = 0; nf < 4; nf++) {
                uint32_t addr = b_base + (uint32_t)(nf * 8 * PAD) * 2 + koff;
                asm volatile(
                    "ldmatrix.sync.aligned.m8n8.x2.shared.b16 {%0,%1}, [%2];"
                    : "=r"(b[nf][0]), "=r"(b[nf][1])
                    : "r"(addr));
            }
            #pragma unroll
            for (int mf = 0; mf < 4; mf++)
                #pragma unroll
                for (int nf = 0; nf < 4; nf++) {
                    asm volatile(
                        "mma.sync.aligned.m16n8k16.row.col.f32.bf16.bf16.f32 "
                        "{%0,%1,%2,%3}, {%4,%5,%6,%7}, {%8,%9}, {%0,%1,%2,%3};"
                        : "+f"(c[mf][nf][0]), "+f"(c[mf][nf][1]),
                          "+f"(c[mf][nf][2]), "+f"(c[mf][nf][3])
                        : "r"(a[mf][0]), "r"(a[mf][1]), "r"(a[mf][2]), "r"(a[mf][3]),
                          "r"(b[nf][0]), "r"(b[nf][1]));
                }
        }
        __syncthreads();
    }

    // ---- epilogue: c0,c1 -> (m, n..n+1); c2,c3 -> (m+8, n..n+1)
    #pragma unroll
    for (int nf = 0; nf < 4; nf++) {
        const int n = col0 + warp_n * 32 + nf * 8 + (lane & 3) * 2;
        float bx = bias0 ? bias0[n]     : 0.0f;
        float by = bias0 ? bias0[n + 1] : 0.0f;
        if (bias1) { bx += bias1[n]; by += bias1[n + 1]; }
        #pragma unroll
        for (int mf = 0; mf < 4; mf++) {
            const int m = row0 + warp_m * 64 + mf * 16 + (lane >> 2);
            #pragma unroll
            for (int half = 0; half < 2; half++) {
                const int mm = m + half * 8;
                float v0 = c[mf][nf][half * 2 + 0] + bx;
                float v1 = c[mf][nf][half * 2 + 1] + by;
                if (C) {
                    *reinterpret_cast<float2*>(C + (size_t)mm * Nglob + n) =
                        make_float2(v0, v1);
                }
                if (Csplit) {
                    __nv_bfloat162 hh, ll;
                    hh.x = __float2bfloat16_rn(v0);
                    hh.y = __float2bfloat16_rn(v1);
                    ll.x = __float2bfloat16_rn(v0 - __bfloat162float(hh.x));
                    ll.y = __float2bfloat16_rn(v1 - __bfloat162float(hh.y));
                    __nv_bfloat16* rp = Csplit + (size_t)mm * (3 * Nglob);
                    *reinterpret_cast<__nv_bfloat162*>(rp + n)              = hh;
                    *reinterpret_cast<__nv_bfloat162*>(rp + Nglob + n)      = ll;
                    *reinterpret_cast<__nv_bfloat162*>(rp + 2 * Nglob + n)  = hh;
                }
            }
        }
    }
}

// ---------------------------------------------------------------------------
// Fused per-step LSTM kernel (unchanged from the passing round-3 kernel)
// ---------------------------------------------------------------------------
__global__ __launch_bounds__(256)
void lstm_step(const float* __restrict__ Whh1,
               const float* __restrict__ Whh2,
               float* __restrict__ out, int t)
{
    const int z = blockIdx.z;
    const float* __restrict__ W = z ? Whh2 : Whh1;
    const int toff = z ? (T_ - 1 - t) : t;
    const int rbuf = t & 1;
    const float* __restrict__ hread  = g_h[z][rbuf];
    float* __restrict__       hwrite = g_h[z][rbuf ^ 1];

    __shared__ float Hs[16][68];
    __shared__ float Ws[4][16][34];

    const int tid  = threadIdx.x;
    const int row0 = blockIdx.y * 64;
    const int col0 = blockIdx.x * 32;
    const int jt   = tid & 15;
    const int bt   = tid >> 4;

    float acc[4][4][2] = {};

    for (int k0 = 0; k0 < H_; k0 += 16) {
        {
            int r = tid >> 2, kq = (tid & 3) << 2;
            float4 v = *reinterpret_cast<const float4*>(
                &hread[(row0 + r) * H_ + k0 + kq]);
            Hs[kq + 0][r] = v.x; Hs[kq + 1][r] = v.y;
            Hs[kq + 2][r] = v.z; Hs[kq + 3][r] = v.w;
        }
        #pragma unroll
        for (int i = 0; i < 2; i++) {
            int f  = tid + i * 256;
            int g  = f >> 7;
            int r  = (f >> 2) & 31;
            int kq = (f & 3) << 2;
            float4 v = *reinterpret_cast<const float4*>(
                &W[(size_t)(g * H_ + col0 + r) * H_ + k0 + kq]);
            Ws[g][kq + 0][r] = v.x; Ws[g][kq + 1][r] = v.y;
            Ws[g][kq + 2][r] = v.z; Ws[g][kq + 3][r] = v.w;
        }
        __syncthreads();

        #pragma unroll
        for (int k = 0; k < 16; k++) {
            float4 a4 = *reinterpret_cast<const float4*>(&Hs[k][bt * 4]);
            float a[4] = {a4.x, a4.y, a4.z, a4.w};
            #pragma unroll
            for (int g = 0; g < 4; g++) {
                float2 b2 = *reinterpret_cast<const float2*>(&Ws[g][k][jt * 2]);
                #pragma unroll
                for (int i = 0; i < 4; i++) {
                    acc[g][i][0] = fmaf(a[i], b2.x, acc[g][i][0]);
                    acc[g][i][1] = fmaf(a[i], b2.y, acc[g][i][1]);
                }
            }
        }
        __syncthreads();
    }

    const int j0 = col0 + jt * 2;
    #pragma unroll
    for (int i = 0; i < 4; i++) {
        const int brow = row0 + bt * 4 + i;
        const float* __restrict__ Apre =
            g_A[z] + ((size_t)brow * T_ + toff) * (size_t)G4H;

        float2 ai = *reinterpret_cast<const float2*>(&Apre[0 * H_ + j0]);
        float2 af = *reinterpret_cast<const float2*>(&Apre[1 * H_ + j0]);
        float2 ag = *reinterpret_cast<const float2*>(&Apre[2 * H_ + j0]);
        float2 ao = *reinterpret_cast<const float2*>(&Apre[3 * H_ + j0]);
        float2 c2 = *reinterpret_cast<const float2*>(&g_c[z][brow * H_ + j0]);

        float gi0 = acc[0][i][0] + ai.x, gi1 = acc[0][i][1] + ai.y;
        float gf0 = acc[1][i][0] + af.x, gf1 = acc[1][i][1] + af.y;
        float gg0 = acc[2][i][0] + ag.x, gg1 = acc[2][i][1] + ag.y;
        float go0 = acc[3][i][0] + ao.x, go1 = acc[3][i][1] + ao.y;

        float si0 = 1.0f / (1.0f + expf(-gi0));
        float sf0 = 1.0f / (1.0f + expf(-gf0));
        float so0 = 1.0f / (1.0f + expf(-go0));
        float si1 = 1.0f / (1.0f + expf(-gi1));
        float sf1 = 1.0f / (1.0f + expf(-gf1));
        float so1 = 1.0f / (1.0f + expf(-go1));

        float cn0 = sf0 * c2.x + si0 * tanhf(gg0);
        float cn1 = sf1 * c2.y + si1 * tanhf(gg1);
        float hn0 = so0 * tanhf(cn0);
        float hn1 = so1 * tanhf(cn1);

        *reinterpret_cast<float2*>(&g_c[z][brow * H_ + j0]) = make_float2(cn0, cn1);
        *reinterpret_cast<float2*>(&hwrite[brow * H_ + j0]) = make_float2(hn0, hn1);

        size_t oidx = (size_t)z * B_ * T_ * H_
                    + (size_t)brow * T_ * H_ + (size_t)toff * H_ + j0;
        *reinterpret_cast<float2*>(&out[oidx]) = make_float2(hn0, hn1);
    }
}

__global__ void init_state_kernel()
{
    int idx = blockIdx.x * blockDim.x + threadIdx.x;
    if (idx < B_ * H_) {
        g_h[0][0][idx] = 0.0f; g_h[1][0][idx] = 0.0f;
        g_c[0][idx]    = 0.0f; g_c[1][idx]    = 0.0f;
    }
}

// ---------------------------------------------------------------------------
extern "C" void kernel_launch(void* const* d_in, const int* in_sizes, int n_in,
                              void* d_out, int out_size)
{
    const float* video = (const float*)d_in[0];   // (B, T, F)
    const float* W_e   = (const float*)d_in[1];   // (P, F)
    const float* b_e   = (const float*)d_in[2];   // (P,)
    const float* W_ih1 = (const float*)d_in[3];   // (4H, P)
    const float* W_hh1 = (const float*)d_in[4];   // (4H, H)
    const float* b_ih1 = (const float*)d_in[5];
    const float* b_hh1 = (const float*)d_in[6];
    const float* W_ih2 = (const float*)d_in[7];
    const float* W_hh2 = (const float*)d_in[8];
    const float* b_ih2 = (const float*)d_in[9];
    const float* b_hh2 = (const float*)d_in[10];
    float* out = (float*)d_out;

    __nv_bfloat16 *dVid, *dWe, *dWih, *dVs;
    float *dA;
    cudaGetSymbolAddress((void**)&dVid, g_vidS);
    cudaGetSymbolAddress((void**)&dWe,  g_WeS);
    cudaGetSymbolAddress((void**)&dWih, g_WihS);
    cudaGetSymbolAddress((void**)&dVs,  g_vS);
    cudaGetSymbolAddress((void**)&dA,   g_A);
    __nv_bfloat16* dWih0 = dWih;
    __nv_bfloat16* dWih1 = dWih + (size_t)G4H * 3 * P_;
    float* dA0 = dA;
    float* dA1 = dA + (size_t)BT * G4H;

    // split conversions
    size_t nvid = (size_t)BT * F_;
    split3_kernel<<<(unsigned)((nvid / 4 + 255) / 256), 256>>>(video, dVid, 11, 0, nvid);
    size_t nwe = (size_t)P_ * F_;
    split3_kernel<<<(unsigned)((nwe / 4 + 255) / 256), 256>>>(W_e, dWe, 11, 1, nwe);
    size_t nwi = (size_t)G4H * P_;
    split3_kernel<<<(unsigned)((nwi / 4 + 255) / 256), 256>>>(W_ih1, dWih0, 9, 1, nwi);
    split3_kernel<<<(unsigned)((nwi / 4 + 255) / 256), 256>>>(W_ih2, dWih1, 9, 1, nwi);

    // Phase 1: v = X @ W_e.T + b_e   -> g_vS (split bf16, fused)   Kt=6144
    gemm_mma_split<<<dim3(P_ / 128, BT / 128), 256>>>(
        dVid, dWe, 3 * F_, P_, b_e, nullptr, nullptr, dVs);

    // Phase 2: A = v @ W_ih.T + (b_ih + b_hh)  -> g_A (fp32) x2    Kt=1536
    gemm_mma_split<<<dim3(G4H / 128, BT / 128), 256>>>(
        dVs, dWih0, 3 * P_, G4H, b_ih1, b_hh1, dA0, nullptr);
    gemm_mma_split<<<dim3(G4H / 128, BT / 128), 256>>>(
        dVs, dWih1, 3 * P_, G4H, b_ih2, b_hh2, dA1, nullptr);

    // recurrence (fp32, proven)
    init_state_kernel<<<(B_ * H_ + 255) / 256, 256>>>();
    for (int t = 0; t < T_; t++) {
        lstm_step<<<dim3(H_ / 32, B_ / 64, 2), 256>>>(W_hh1, W_hh2, out, t);
    }
}